// round 1
// baseline (speedup 1.0000x reference)
#include <cuda_runtime.h>
#include <math.h>

// Problem constants (fixed by the dataset)
#define BQ 32
#define CC 256
#define HH 64
#define WW 64
#define K9 (CC*9)          // 2304

// Scratch: relu(bn1(x)) and conv1 output. Static __device__ arrays (no allocs).
__device__ float g_bufA[(size_t)BQ*CC*HH*WW];
__device__ float g_bufB[(size_t)BQ*CC*HH*WW];

// ---------------------------------------------------------------------------
// Kernel 1: a = relu(bn1(x))   (inference BN, per-channel)
// ---------------------------------------------------------------------------
__global__ void bn_relu_kernel(const float* __restrict__ x,
                               const float* __restrict__ g,
                               const float* __restrict__ be,
                               const float* __restrict__ mu,
                               const float* __restrict__ var,
                               float* __restrict__ out)
{
    int i = blockIdx.x * blockDim.x + threadIdx.x;      // float4 index
    const int n4 = (BQ*CC*HH*WW) / 4;
    if (i >= n4) return;
    // each (b,c) slab is 64*64 = 4096 floats = 1024 float4s
    int c = (i >> 10) & (CC - 1);
    float inv = g[c] * rsqrtf(var[c] + 1e-5f);
    float sh  = be[c] - mu[c] * inv;
    float4 v = ((const float4*)x)[i];
    v.x = fmaxf(fmaf(v.x, inv, sh), 0.f);
    v.y = fmaxf(fmaf(v.y, inv, sh), 0.f);
    v.z = fmaxf(fmaf(v.z, inv, sh), 0.f);
    v.w = fmaxf(fmaf(v.w, inv, sh), 0.f);
    ((float4*)out)[i] = v;
}

// ---------------------------------------------------------------------------
// Kernel 2: per-sample 3x3 conv (SAME, stride 1), weights synthesized on the
// fly as  tw[b, co, ci, kh, kw] = h_b * wv[idx] + bv[idx]  (HD = 1).
//
// Grid: (H, Cout/64, B).  Block: 128 threads.
// CTA computes a [64 co x 64 px] output tile for one row h of one sample.
// Thread tile: 4 co x 8 px.  K-loop over input channels in chunks of 8.
//
// mode 1: epilogue = bn2 + relu     (writes conv1 output)
// mode 2: epilogue = + addsrc       (residual; writes final output)
// ---------------------------------------------------------------------------
__global__ __launch_bounds__(128)
void hyperconv_kernel(const float* __restrict__ in,
                      float* __restrict__ out,
                      const float* __restrict__ wv,
                      const float* __restrict__ bv,
                      const float* __restrict__ hin,
                      const float* __restrict__ g2,
                      const float* __restrict__ be2,
                      const float* __restrict__ mu2,
                      const float* __restrict__ var2,
                      const float* __restrict__ addsrc,
                      int mode)
{
    __shared__ __align__(16) float Ws[72][64];     // [kk = ci_l*9+kh*3+kw][co_l]
    __shared__ float Xs[8][3][66];                 // [ci_l][kh][col+1], halo cols

    const int h   = blockIdx.x;        // output row
    const int cot = blockIdx.y;        // Cout tile, 0..3
    const int b   = blockIdx.z;        // sample

    const int tid = threadIdx.x;
    const int tm  = tid & 15;          // 16 threads across co
    const int tn  = tid >> 4;          // 8 threads across px
    const int tm4 = tm * 4;
    const int tn8 = tn * 8;

    const float hb = 0.5f + hin[b] * (1.0f / 64.0f);
    const int coBase = cot * 64;
    const float* inB = in + (size_t)b * CC * HH * WW;

    float acc[4][8];
    #pragma unroll
    for (int i = 0; i < 4; ++i)
        #pragma unroll
        for (int j = 0; j < 8; ++j)
            acc[i][j] = 0.f;

    const int co_l = tid >> 1;         // 0..63 (one co per thread-pair)
    const int half = tid & 1;          // which 36-float half of the 72-k chunk

    for (int cc = 0; cc < CC / 8; ++cc) {
        const int ci0 = cc * 8;
        __syncthreads();   // protect smem from previous iteration's readers

        // --- stage weights: Ws[kk][co] = hb * w + b  (72 contiguous k per co)
        {
            const int gco  = coBase + co_l;
            const int base = gco * K9 + ci0 * 9 + half * 36;   // 16B-aligned
            const float4* w4 = (const float4*)(wv + base);
            const float4* b4 = (const float4*)(bv + base);
            #pragma unroll
            for (int m = 0; m < 9; ++m) {
                float4 a  = w4[m];
                float4 c4 = b4[m];
                int kk = half * 36 + m * 4;
                Ws[kk + 0][co_l] = fmaf(hb, a.x, c4.x);
                Ws[kk + 1][co_l] = fmaf(hb, a.y, c4.y);
                Ws[kk + 2][co_l] = fmaf(hb, a.z, c4.z);
                Ws[kk + 3][co_l] = fmaf(hb, a.w, c4.w);
            }
        }

        // --- stage input: 8 channels x 3 rows x 66 cols (zero-padded halo)
        for (int i = tid; i < 8 * 3 * 66; i += 128) {
            int ci  = i / 198;
            int rem = i - ci * 198;
            int r   = rem / 66;
            int cix = rem - r * 66;
            int gr  = h + r - 1;
            int gc  = cix - 1;
            float v = 0.f;
            if ((unsigned)gr < HH && (unsigned)gc < WW)
                v = inB[((size_t)(ci0 + ci) * HH + gr) * WW + gc];
            Xs[ci][r][cix] = v;
        }
        __syncthreads();

        // --- compute: 96 FFMA per (ci,kh) per thread, 13 LDS
        #pragma unroll 1
        for (int ci = 0; ci < 8; ++ci) {
            #pragma unroll
            for (int kh = 0; kh < 3; ++kh) {
                float xv[10];
                #pragma unroll
                for (int c = 0; c < 10; ++c)
                    xv[c] = Xs[ci][kh][tn8 + c];
                #pragma unroll
                for (int kw = 0; kw < 3; ++kw) {
                    const float4 wq = *(const float4*)&Ws[ci * 9 + kh * 3 + kw][tm4];
                    #pragma unroll
                    for (int j = 0; j < 8; ++j) {
                        acc[0][j] = fmaf(wq.x, xv[j + kw], acc[0][j]);
                        acc[1][j] = fmaf(wq.y, xv[j + kw], acc[1][j]);
                        acc[2][j] = fmaf(wq.z, xv[j + kw], acc[2][j]);
                        acc[3][j] = fmaf(wq.w, xv[j + kw], acc[3][j]);
                    }
                }
            }
        }
    }

    // --- epilogue ---
    #pragma unroll
    for (int i = 0; i < 4; ++i) {
        const int gco = coBase + tm4 + i;
        float* orow = out + (((size_t)b * CC + gco) * HH + h) * WW + tn8;
        float4 r0, r1;
        if (mode == 1) {
            float inv = g2[gco] * rsqrtf(var2[gco] + 1e-5f);
            float sh  = be2[gco] - mu2[gco] * inv;
            r0.x = fmaxf(fmaf(acc[i][0], inv, sh), 0.f);
            r0.y = fmaxf(fmaf(acc[i][1], inv, sh), 0.f);
            r0.z = fmaxf(fmaf(acc[i][2], inv, sh), 0.f);
            r0.w = fmaxf(fmaf(acc[i][3], inv, sh), 0.f);
            r1.x = fmaxf(fmaf(acc[i][4], inv, sh), 0.f);
            r1.y = fmaxf(fmaf(acc[i][5], inv, sh), 0.f);
            r1.z = fmaxf(fmaf(acc[i][6], inv, sh), 0.f);
            r1.w = fmaxf(fmaf(acc[i][7], inv, sh), 0.f);
        } else {
            const float* xr = addsrc + (((size_t)b * CC + gco) * HH + h) * WW + tn8;
            float4 x0 = ((const float4*)xr)[0];
            float4 x1 = ((const float4*)xr)[1];
            r0.x = acc[i][0] + x0.x;
            r0.y = acc[i][1] + x0.y;
            r0.z = acc[i][2] + x0.z;
            r0.w = acc[i][3] + x0.w;
            r1.x = acc[i][4] + x1.x;
            r1.y = acc[i][5] + x1.y;
            r1.z = acc[i][6] + x1.z;
            r1.w = acc[i][7] + x1.w;
        }
        ((float4*)orow)[0] = r0;
        ((float4*)orow)[1] = r1;
    }
}

// ---------------------------------------------------------------------------
// kernel_launch — inputs in metadata order:
//  0:x 1:h_in 2:bn1_gamma 3:bn1_beta 4:bn1_mean 5:bn1_var 6:w1 7:b1
//  8:bn2_gamma 9:bn2_beta 10:bn2_mean 11:bn2_var 12:w2 13:b2
// ---------------------------------------------------------------------------
extern "C" void kernel_launch(void* const* d_in, const int* in_sizes, int n_in,
                              void* d_out, int out_size)
{
    const float* x    = (const float*)d_in[0];
    const float* hin  = (const float*)d_in[1];
    const float* g1   = (const float*)d_in[2];
    const float* be1  = (const float*)d_in[3];
    const float* mu1  = (const float*)d_in[4];
    const float* var1 = (const float*)d_in[5];
    const float* w1   = (const float*)d_in[6];
    const float* b1   = (const float*)d_in[7];
    const float* g2   = (const float*)d_in[8];
    const float* be2  = (const float*)d_in[9];
    const float* mu2  = (const float*)d_in[10];
    const float* var2 = (const float*)d_in[11];
    const float* w2   = (const float*)d_in[12];
    const float* b2   = (const float*)d_in[13];
    float* out = (float*)d_out;

    float* bufA = nullptr;
    float* bufB = nullptr;
    cudaGetSymbolAddress((void**)&bufA, g_bufA);
    cudaGetSymbolAddress((void**)&bufB, g_bufB);

    // 1) a = relu(bn1(x))
    {
        const int n4 = (BQ*CC*HH*WW) / 4;
        int threads = 256;
        int blocks = (n4 + threads - 1) / threads;
        bn_relu_kernel<<<blocks, threads>>>(x, g1, be1, mu1, var1, bufA);
    }

    dim3 grid(HH, CC / 64, BQ);   // (64 rows, 4 co-tiles, 32 samples)

    // 2) conv1 + bn2 + relu -> bufB
    hyperconv_kernel<<<grid, 128>>>(bufA, bufB, w1, b1, hin,
                                    g2, be2, mu2, var2,
                                    nullptr, 1);

    // 3) conv2 + residual(x) -> out
    hyperconv_kernel<<<grid, 128>>>(bufB, out, w2, b2, hin,
                                    g2, be2, mu2, var2,   // unused in mode 2
                                    x, 2);
}

// round 2
// speedup vs baseline: 1.1198x; 1.1198x over previous
#include <cuda_runtime.h>
#include <math.h>

#define BQ 32
#define CC 256
#define HH 64
#define WW 64
#define K9 (CC*9)          // 2304

// Scratch: conv1 output (only intermediate left; bn1 is fused into conv1).
__device__ float g_bufB[(size_t)BQ*CC*HH*WW];

// Packed dual-FMA: d.lo = a.lo*b.lo + c.lo ; d.hi = a.hi*b.hi + c.hi
__device__ __forceinline__ unsigned long long ffma2(unsigned long long a,
                                                    unsigned long long b,
                                                    unsigned long long c)
{
    asm("fma.rn.f32x2 %0, %1, %2, %0;" : "+l"(c) : "l"(a), "l"(b));
    return c;
}
__device__ __forceinline__ float lo32(unsigned long long v) {
    return __uint_as_float((unsigned)(v & 0xffffffffull));
}
__device__ __forceinline__ float hi32(unsigned long long v) {
    return __uint_as_float((unsigned)(v >> 32));
}

// ---------------------------------------------------------------------------
// Per-sample 3x3 conv (SAME, stride 1), weights synthesized on the fly:
//   tw[b, co, ci, kh, kw] = h_b * wv[idx] + bv[idx]     (HD = 1)
//
// Grid: (H/2, Cout/64, B). Block: 128 threads.
// CTA tile: 64 co x (2 rows x 64 cols). Thread tile: 8 co x 8 px.
// Inner loop uses packed fma.rn.f32x2 (FFMA2): accumulators hold co-pairs,
// weight pairs come contiguous from SMEM, x is stored duplicated (v,v) in
// SMEM so broadcast operands are a single LDS.64.
//
// mode 1: input = relu(bn_in(in)) fused at staging; epilogue = bn_out + relu
// mode 2: input raw;                                epilogue = + addsrc
// ---------------------------------------------------------------------------
__global__ __launch_bounds__(128, 2)
void hyperconv_kernel(const float* __restrict__ in,
                      float* __restrict__ out,
                      const float* __restrict__ wv,
                      const float* __restrict__ bv,
                      const float* __restrict__ hin,
                      const float* __restrict__ giA, const float* __restrict__ biA,
                      const float* __restrict__ miA, const float* __restrict__ viA,
                      const float* __restrict__ goB, const float* __restrict__ boB,
                      const float* __restrict__ moB, const float* __restrict__ voB,
                      const float* __restrict__ addsrc,
                      int mode)
{
    __shared__ __align__(16) float  Ws[72][64];        // [kk=ci*9+kh*3+kw][co]
    __shared__ __align__(16) float2 Xs[8][4][66];      // duplicated (v,v), halo cols
    __shared__ float sInv[CC];                         // fused input-BN scale
    __shared__ float sSh[CC];                          // fused input-BN shift

    const int h0  = blockIdx.x * 2;     // first of 2 output rows
    const int cot = blockIdx.y;         // 64-co tile, 0..3
    const int b   = blockIdx.z;         // sample

    const int tid = threadIdx.x;
    const int tm  = tid & 7;            // 8 threads across co
    const int tn  = tid >> 3;           // 16 threads across px
    const int tm8 = tm * 8;             // thread's first co (local)
    const int row = tn >> 3;            // 0/1 within the row pair
    const int c0  = (tn & 7) * 8;       // thread's first column

    const float hb = 0.5f + hin[b] * (1.0f / 64.0f);
    const int coBase = cot * 64;
    const float* inB = in + (size_t)b * CC * HH * WW;

    // Precompute fused input-BN coefficients once (mode 1 only).
    if (mode == 1) {
        for (int c = tid; c < CC; c += 128) {
            float inv = giA[c] * rsqrtf(viA[c] + 1e-5f);
            sInv[c] = inv;
            sSh[c]  = biA[c] - miA[c] * inv;
        }
    }
    // (first __syncthreads below covers this)

    unsigned long long acc[4][8];       // [co-pair][px]
    #pragma unroll
    for (int p = 0; p < 4; ++p)
        #pragma unroll
        for (int j = 0; j < 8; ++j)
            acc[p][j] = 0ull;

    const int co_l = tid >> 1;          // weight staging: one co per thread pair
    const int half = tid & 1;           // which 36-float half of the 72-k chunk

    for (int cc = 0; cc < CC / 8; ++cc) {
        const int ci0 = cc * 8;
        __syncthreads();                // also orders sInv/sSh on first iter

        // --- stage weights: Ws[kk][co] = hb * w + b
        {
            const int gco  = coBase + co_l;
            const int base = gco * K9 + ci0 * 9 + half * 36;   // 16B-aligned
            const float4* w4 = (const float4*)(wv + base);
            const float4* b4 = (const float4*)(bv + base);
            #pragma unroll
            for (int m = 0; m < 9; ++m) {
                float4 a  = w4[m];
                float4 c4 = b4[m];
                int kk = half * 36 + m * 4;
                Ws[kk + 0][co_l] = fmaf(hb, a.x, c4.x);
                Ws[kk + 1][co_l] = fmaf(hb, a.y, c4.y);
                Ws[kk + 2][co_l] = fmaf(hb, a.z, c4.z);
                Ws[kk + 3][co_l] = fmaf(hb, a.w, c4.w);
            }
        }

        // --- stage input: 8 ch x 4 rows (h0-1..h0+2) x 66 cols, duplicated
        for (int i = tid; i < 8 * 4 * 66; i += 128) {
            int ci  = i / 264;
            int rem = i - ci * 264;
            int r   = rem / 66;
            int cx  = rem - r * 66;
            int gr  = h0 + r - 1;
            int gc  = cx - 1;
            float v = 0.f;
            if ((unsigned)gr < HH && (unsigned)gc < WW)
                v = inB[((size_t)(ci0 + ci) * HH + gr) * WW + gc];
            if (mode == 1)
                v = fmaxf(fmaf(v, sInv[ci0 + ci], sSh[ci0 + ci]), 0.f);
            Xs[ci][r][cx] = make_float2(v, v);
        }
        __syncthreads();

        // --- compute: per (ci,kh): 10 LDS.64 + 6 LDS.128 + 96 FFMA2 (192 MACs)
        #pragma unroll 1
        for (int ci = 0; ci < 8; ++ci) {
            #pragma unroll
            for (int kh = 0; kh < 3; ++kh) {
                unsigned long long xd[10];
                const float2* xrow = &Xs[ci][row + kh][c0];
                #pragma unroll
                for (int c = 0; c < 10; ++c)
                    xd[c] = *(const unsigned long long*)&xrow[c];
                #pragma unroll
                for (int kw = 0; kw < 3; ++kw) {
                    const int kk = ci * 9 + kh * 3 + kw;
                    const ulonglong2 wA = *(const ulonglong2*)&Ws[kk][tm8];
                    const ulonglong2 wB = *(const ulonglong2*)&Ws[kk][tm8 + 4];
                    #pragma unroll
                    for (int j = 0; j < 8; ++j) {
                        acc[0][j] = ffma2(wA.x, xd[j + kw], acc[0][j]);
                        acc[1][j] = ffma2(wA.y, xd[j + kw], acc[1][j]);
                        acc[2][j] = ffma2(wB.x, xd[j + kw], acc[2][j]);
                        acc[3][j] = ffma2(wB.y, xd[j + kw], acc[3][j]);
                    }
                }
            }
        }
    }

    // --- epilogue: 8 co x 8 px per thread ---
    const int hrow = h0 + row;
    #pragma unroll
    for (int i = 0; i < 8; ++i) {
        const int p = i >> 1;
        const int gco = coBase + tm8 + i;
        float v[8];
        if (i & 1) {
            #pragma unroll
            for (int j = 0; j < 8; ++j) v[j] = hi32(acc[p][j]);
        } else {
            #pragma unroll
            for (int j = 0; j < 8; ++j) v[j] = lo32(acc[p][j]);
        }
        float* orow = out + (((size_t)b * CC + gco) * HH + hrow) * WW + c0;
        float4 r0, r1;
        if (mode == 1) {
            float inv = goB[gco] * rsqrtf(voB[gco] + 1e-5f);
            float sh  = boB[gco] - moB[gco] * inv;
            r0.x = fmaxf(fmaf(v[0], inv, sh), 0.f);
            r0.y = fmaxf(fmaf(v[1], inv, sh), 0.f);
            r0.z = fmaxf(fmaf(v[2], inv, sh), 0.f);
            r0.w = fmaxf(fmaf(v[3], inv, sh), 0.f);
            r1.x = fmaxf(fmaf(v[4], inv, sh), 0.f);
            r1.y = fmaxf(fmaf(v[5], inv, sh), 0.f);
            r1.z = fmaxf(fmaf(v[6], inv, sh), 0.f);
            r1.w = fmaxf(fmaf(v[7], inv, sh), 0.f);
        } else {
            const float* xr = addsrc + (((size_t)b * CC + gco) * HH + hrow) * WW + c0;
            float4 x0 = ((const float4*)xr)[0];
            float4 x1 = ((const float4*)xr)[1];
            r0.x = v[0] + x0.x;  r0.y = v[1] + x0.y;
            r0.z = v[2] + x0.z;  r0.w = v[3] + x0.w;
            r1.x = v[4] + x1.x;  r1.y = v[5] + x1.y;
            r1.z = v[6] + x1.z;  r1.w = v[7] + x1.w;
        }
        ((float4*)orow)[0] = r0;
        ((float4*)orow)[1] = r1;
    }
}

// ---------------------------------------------------------------------------
// kernel_launch — inputs in metadata order:
//  0:x 1:h_in 2:bn1_gamma 3:bn1_beta 4:bn1_mean 5:bn1_var 6:w1 7:b1
//  8:bn2_gamma 9:bn2_beta 10:bn2_mean 11:bn2_var 12:w2 13:b2
// ---------------------------------------------------------------------------
extern "C" void kernel_launch(void* const* d_in, const int* in_sizes, int n_in,
                              void* d_out, int out_size)
{
    const float* x    = (const float*)d_in[0];
    const float* hin  = (const float*)d_in[1];
    const float* g1   = (const float*)d_in[2];
    const float* be1  = (const float*)d_in[3];
    const float* mu1  = (const float*)d_in[4];
    const float* var1 = (const float*)d_in[5];
    const float* w1   = (const float*)d_in[6];
    const float* b1   = (const float*)d_in[7];
    const float* g2   = (const float*)d_in[8];
    const float* be2  = (const float*)d_in[9];
    const float* mu2  = (const float*)d_in[10];
    const float* var2 = (const float*)d_in[11];
    const float* w2   = (const float*)d_in[12];
    const float* b2   = (const float*)d_in[13];
    float* out = (float*)d_out;

    float* bufB = nullptr;
    cudaGetSymbolAddress((void**)&bufB, g_bufB);

    dim3 grid(HH / 2, CC / 64, BQ);    // (32 row-pairs, 4 co-tiles, 32 samples)

    // 1) conv1( relu(bn1(x)) ) + bn2 + relu -> bufB    (bn1 fused at staging)
    hyperconv_kernel<<<grid, 128>>>(x, bufB, w1, b1, hin,
                                    g1, be1, mu1, var1,
                                    g2, be2, mu2, var2,
                                    nullptr, 1);

    // 2) conv2(bufB) + residual(x) -> out
    hyperconv_kernel<<<grid, 128>>>(bufB, out, w2, b2, hin,
                                    g2, be2, mu2, var2,   // unused in mode 2
                                    g2, be2, mu2, var2,   // unused in mode 2
                                    x, 2);
}

// round 3
// speedup vs baseline: 1.1215x; 1.0015x over previous
#include <cuda_runtime.h>
#include <math.h>

#define BQ 32
#define CC 256
#define HH 64
#define WW 64
#define K9 (CC*9)          // 2304

// Scratch: conv1 output (only intermediate left; bn1 is fused into conv1).
__device__ float g_bufB[(size_t)BQ*CC*HH*WW];

// Packed dual-FMA: d.lo = a.lo*b.lo + c.lo ; d.hi = a.hi*b.hi + c.hi
__device__ __forceinline__ unsigned long long ffma2(unsigned long long a,
                                                    unsigned long long b,
                                                    unsigned long long c)
{
    asm("fma.rn.f32x2 %0, %1, %2, %0;" : "+l"(c) : "l"(a), "l"(b));
    return c;
}
__device__ __forceinline__ float lo32(unsigned long long v) {
    return __uint_as_float((unsigned)(v & 0xffffffffull));
}
__device__ __forceinline__ float hi32(unsigned long long v) {
    return __uint_as_float((unsigned)(v >> 32));
}

// ---------------------------------------------------------------------------
// Per-sample 3x3 conv (SAME, stride 1), weights synthesized on the fly:
//   tw[b, co, ci, kh, kw] = h_b * wv[idx] + bv[idx]     (HD = 1)
//
// Grid: (H/2, Cout/64, B). Block: 128 threads.
// CTA tile: 64 co x (2 rows x 64 cols). Thread tile: 8 co x 8 px.
// Inner loop uses packed fma.rn.f32x2 (FFMA2): accumulators hold co-pairs,
// weight pairs come contiguous from SMEM, x is stored duplicated (v,v) in
// SMEM so broadcast operands are a single LDS.64.
//
// mode 1: input = relu(bn_in(in)) fused at staging; epilogue = bn_out + relu
// mode 2: input raw;                                epilogue = + addsrc
// ---------------------------------------------------------------------------
__global__ __launch_bounds__(128, 2)
void hyperconv_kernel(const float* __restrict__ in,
                      float* __restrict__ out,
                      const float* __restrict__ wv,
                      const float* __restrict__ bv,
                      const float* __restrict__ hin,
                      const float* __restrict__ giA, const float* __restrict__ biA,
                      const float* __restrict__ miA, const float* __restrict__ viA,
                      const float* __restrict__ goB, const float* __restrict__ boB,
                      const float* __restrict__ moB, const float* __restrict__ voB,
                      const float* __restrict__ addsrc,
                      int mode)
{
    __shared__ __align__(16) float  Ws[72][64];        // [kk=ci*9+kh*3+kw][co]
    __shared__ __align__(16) float2 Xs[8][4][66];      // duplicated (v,v), halo cols
    __shared__ float sInv[CC];                         // fused input-BN scale
    __shared__ float sSh[CC];                          // fused input-BN shift

    const int h0  = blockIdx.x * 2;     // first of 2 output rows
    const int cot = blockIdx.y;         // 64-co tile, 0..3
    const int b   = blockIdx.z;         // sample

    const int tid = threadIdx.x;
    const int tm  = tid & 7;            // 8 threads across co
    const int tn  = tid >> 3;           // 16 threads across px
    const int tm8 = tm * 8;             // thread's first co (local)
    const int row = tn >> 3;            // 0/1 within the row pair
    const int c0  = (tn & 7) * 8;       // thread's first column

    const float hb = 0.5f + hin[b] * (1.0f / 64.0f);
    const int coBase = cot * 64;
    const float* inB = in + (size_t)b * CC * HH * WW;

    // Precompute fused input-BN coefficients once (mode 1 only).
    if (mode == 1) {
        for (int c = tid; c < CC; c += 128) {
            float inv = giA[c] * rsqrtf(viA[c] + 1e-5f);
            sInv[c] = inv;
            sSh[c]  = biA[c] - miA[c] * inv;
        }
    }
    // (first __syncthreads below covers this)

    unsigned long long acc[4][8];       // [co-pair][px]
    #pragma unroll
    for (int p = 0; p < 4; ++p)
        #pragma unroll
        for (int j = 0; j < 8; ++j)
            acc[p][j] = 0ull;

    const int co_l = tid >> 1;          // weight staging: one co per thread pair
    const int half = tid & 1;           // which 36-float half of the 72-k chunk

    for (int cc = 0; cc < CC / 8; ++cc) {
        const int ci0 = cc * 8;
        __syncthreads();                // also orders sInv/sSh on first iter

        // --- stage weights: Ws[kk][co] = hb * w + b
        {
            const int gco  = coBase + co_l;
            const int base = gco * K9 + ci0 * 9 + half * 36;   // 16B-aligned
            const float4* w4 = (const float4*)(wv + base);
            const float4* b4 = (const float4*)(bv + base);
            #pragma unroll
            for (int m = 0; m < 9; ++m) {
                float4 a  = w4[m];
                float4 c4 = b4[m];
                int kk = half * 36 + m * 4;
                Ws[kk + 0][co_l] = fmaf(hb, a.x, c4.x);
                Ws[kk + 1][co_l] = fmaf(hb, a.y, c4.y);
                Ws[kk + 2][co_l] = fmaf(hb, a.z, c4.z);
                Ws[kk + 3][co_l] = fmaf(hb, a.w, c4.w);
            }
        }

        // --- stage input: 8 ch x 4 rows (h0-1..h0+2) x 66 cols, duplicated
        for (int i = tid; i < 8 * 4 * 66; i += 128) {
            int ci  = i / 264;
            int rem = i - ci * 264;
            int r   = rem / 66;
            int cx  = rem - r * 66;
            int gr  = h0 + r - 1;
            int gc  = cx - 1;
            float v = 0.f;
            if ((unsigned)gr < HH && (unsigned)gc < WW)
                v = inB[((size_t)(ci0 + ci) * HH + gr) * WW + gc];
            if (mode == 1)
                v = fmaxf(fmaf(v, sInv[ci0 + ci], sSh[ci0 + ci]), 0.f);
            Xs[ci][r][cx] = make_float2(v, v);
        }
        __syncthreads();

        // --- compute: per (ci,kh): 10 LDS.64 + 6 LDS.128 + 96 FFMA2 (192 MACs)
        #pragma unroll 1
        for (int ci = 0; ci < 8; ++ci) {
            #pragma unroll
            for (int kh = 0; kh < 3; ++kh) {
                unsigned long long xd[10];
                const float2* xrow = &Xs[ci][row + kh][c0];
                #pragma unroll
                for (int c = 0; c < 10; ++c)
                    xd[c] = *(const unsigned long long*)&xrow[c];
                #pragma unroll
                for (int kw = 0; kw < 3; ++kw) {
                    const int kk = ci * 9 + kh * 3 + kw;
                    const ulonglong2 wA = *(const ulonglong2*)&Ws[kk][tm8];
                    const ulonglong2 wB = *(const ulonglong2*)&Ws[kk][tm8 + 4];
                    #pragma unroll
                    for (int j = 0; j < 8; ++j) {
                        acc[0][j] = ffma2(wA.x, xd[j + kw], acc[0][j]);
                        acc[1][j] = ffma2(wA.y, xd[j + kw], acc[1][j]);
                        acc[2][j] = ffma2(wB.x, xd[j + kw], acc[2][j]);
                        acc[3][j] = ffma2(wB.y, xd[j + kw], acc[3][j]);
                    }
                }
            }
        }
    }

    // --- epilogue: 8 co x 8 px per thread ---
    const int hrow = h0 + row;
    #pragma unroll
    for (int i = 0; i < 8; ++i) {
        const int p = i >> 1;
        const int gco = coBase + tm8 + i;
        float v[8];
        if (i & 1) {
            #pragma unroll
            for (int j = 0; j < 8; ++j) v[j] = hi32(acc[p][j]);
        } else {
            #pragma unroll
            for (int j = 0; j < 8; ++j) v[j] = lo32(acc[p][j]);
        }
        float* orow = out + (((size_t)b * CC + gco) * HH + hrow) * WW + c0;
        float4 r0, r1;
        if (mode == 1) {
            float inv = goB[gco] * rsqrtf(voB[gco] + 1e-5f);
            float sh  = boB[gco] - moB[gco] * inv;
            r0.x = fmaxf(fmaf(v[0], inv, sh), 0.f);
            r0.y = fmaxf(fmaf(v[1], inv, sh), 0.f);
            r0.z = fmaxf(fmaf(v[2], inv, sh), 0.f);
            r0.w = fmaxf(fmaf(v[3], inv, sh), 0.f);
            r1.x = fmaxf(fmaf(v[4], inv, sh), 0.f);
            r1.y = fmaxf(fmaf(v[5], inv, sh), 0.f);
            r1.z = fmaxf(fmaf(v[6], inv, sh), 0.f);
            r1.w = fmaxf(fmaf(v[7], inv, sh), 0.f);
        } else {
            const float* xr = addsrc + (((size_t)b * CC + gco) * HH + hrow) * WW + c0;
            float4 x0 = ((const float4*)xr)[0];
            float4 x1 = ((const float4*)xr)[1];
            r0.x = v[0] + x0.x;  r0.y = v[1] + x0.y;
            r0.z = v[2] + x0.z;  r0.w = v[3] + x0.w;
            r1.x = v[4] + x1.x;  r1.y = v[5] + x1.y;
            r1.z = v[6] + x1.z;  r1.w = v[7] + x1.w;
        }
        ((float4*)orow)[0] = r0;
        ((float4*)orow)[1] = r1;
    }
}

// ---------------------------------------------------------------------------
// kernel_launch — inputs in metadata order:
//  0:x 1:h_in 2:bn1_gamma 3:bn1_beta 4:bn1_mean 5:bn1_var 6:w1 7:b1
//  8:bn2_gamma 9:bn2_beta 10:bn2_mean 11:bn2_var 12:w2 13:b2
// ---------------------------------------------------------------------------
extern "C" void kernel_launch(void* const* d_in, const int* in_sizes, int n_in,
                              void* d_out, int out_size)
{
    const float* x    = (const float*)d_in[0];
    const float* hin  = (const float*)d_in[1];
    const float* g1   = (const float*)d_in[2];
    const float* be1  = (const float*)d_in[3];
    const float* mu1  = (const float*)d_in[4];
    const float* var1 = (const float*)d_in[5];
    const float* w1   = (const float*)d_in[6];
    const float* b1   = (const float*)d_in[7];
    const float* g2   = (const float*)d_in[8];
    const float* be2  = (const float*)d_in[9];
    const float* mu2  = (const float*)d_in[10];
    const float* var2 = (const float*)d_in[11];
    const float* w2   = (const float*)d_in[12];
    const float* b2   = (const float*)d_in[13];
    float* out = (float*)d_out;

    float* bufB = nullptr;
    cudaGetSymbolAddress((void**)&bufB, g_bufB);

    dim3 grid(HH / 2, CC / 64, BQ);    // (32 row-pairs, 4 co-tiles, 32 samples)

    // 1) conv1( relu(bn1(x)) ) + bn2 + relu -> bufB    (bn1 fused at staging)
    hyperconv_kernel<<<grid, 128>>>(x, bufB, w1, b1, hin,
                                    g1, be1, mu1, var1,
                                    g2, be2, mu2, var2,
                                    nullptr, 1);

    // 2) conv2(bufB) + residual(x) -> out
    hyperconv_kernel<<<grid, 128>>>(bufB, out, w2, b2, hin,
                                    g2, be2, mu2, var2,   // unused in mode 2
                                    g2, be2, mu2, var2,   // unused in mode 2
                                    x, 2);
}